// round 7
// baseline (speedup 1.0000x reference)
#include <cuda_runtime.h>
#include <cstdint>

#define H   2048
#define I   1408
#define E   8
#define T   512
#define I2  2816   // 2*I
#define IW  704    // I/2: act row width in uint32 (bf16 pairs)
#define HW  1024   // H/2: x row width in uint32 (bf16 pairs)

// per-CTA dynamic smem: A bf16 ring 3x16KB @0x0000, B fp32 ring 3x16KB @0xC000
#define SMEMSZ  0x18000   // 96 KB

// ---------------- device scratch (no allocations allowed) ----------------
__device__ int   g_cnt[E];
__device__ int   g_tok[E][T];
__device__ float g_cw [E][T];
__device__ __align__(16) uint32_t g_act_hi[(size_t)E * T * IW];
__device__ __align__(16) uint32_t g_act_lo[(size_t)E * T * IW];
__device__ __align__(16) uint32_t g_x_hi[(size_t)T * HW];
__device__ __align__(16) uint32_t g_x_lo[(size_t)T * HW];

// ---------------- helpers ----------------
__device__ __forceinline__ uint32_t smem_u32(const void* p) {
    uint32_t a;
    asm("{ .reg .u64 t; cvta.to.shared.u64 t, %1; cvt.u32.u64 %0, t; }" : "=r"(a) : "l"(p));
    return a;
}
__device__ __forceinline__ uint32_t packbf(float lo, float hi) {
    uint32_t r;
    asm("cvt.rn.bf16x2.f32 %0, %1, %2;" : "=r"(r) : "f"(hi), "f"(lo));
    return r;
}
__device__ __forceinline__ void split4(float4 v, uint32_t& h0, uint32_t& h1,
                                       uint32_t& l0, uint32_t& l1) {
    h0 = packbf(v.x, v.y);
    h1 = packbf(v.z, v.w);
    float fx = __uint_as_float(h0 << 16), fy = __uint_as_float(h0 & 0xFFFF0000u);
    float fz = __uint_as_float(h1 << 16), fw = __uint_as_float(h1 & 0xFFFF0000u);
    l0 = packbf(v.x - fx, v.y - fy);
    l1 = packbf(v.z - fz, v.w - fw);
}
__device__ __forceinline__ void split2(float2 v, uint32_t& hh, uint32_t& ll) {
    hh = packbf(v.x, v.y);
    ll = packbf(v.x - __uint_as_float(hh << 16), v.y - __uint_as_float(hh & 0xFFFF0000u));
}
__device__ __forceinline__ float2 lds64(uint32_t a) {
    float2 v;
    asm volatile("ld.shared.v2.f32 {%0,%1}, [%2];" : "=f"(v.x), "=f"(v.y) : "r"(a));
    return v;
}
__device__ __forceinline__ void ldsm4(uint32_t* r, uint32_t a) {
    asm volatile("ldmatrix.sync.aligned.m8n8.x4.shared.b16 {%0,%1,%2,%3}, [%4];"
        : "=r"(r[0]), "=r"(r[1]), "=r"(r[2]), "=r"(r[3]) : "r"(a));
}
__device__ __forceinline__ void mma_bf(float* d, const uint32_t* a, uint32_t b0, uint32_t b1) {
    asm volatile("mma.sync.aligned.m16n8k16.row.col.f32.bf16.bf16.f32 "
        "{%0,%1,%2,%3}, {%4,%5,%6,%7}, {%8,%9}, {%0,%1,%2,%3};"
        : "+f"(d[0]), "+f"(d[1]), "+f"(d[2]), "+f"(d[3])
        : "r"(a[0]), "r"(a[1]), "r"(a[2]), "r"(a[3]), "r"(b0), "r"(b1));
}
#define CP16(d_, s_)  asm volatile("cp.async.cg.shared.global [%0], [%1], 16;" :: "r"(d_), "l"(s_))
#define CPCOMMIT()    asm volatile("cp.async.commit_group;" ::)
#define CPWAIT(n_)    asm volatile("cp.async.wait_group %0;" :: "n"(n_))

// ---------------- init (counters only) ----------------
__global__ void k_init() {
    if (threadIdx.x < E) g_cnt[threadIdx.x] = 0;
}

// ---------------- router: also zeroes out row t and splits x row t ----------------
__global__ void k_router(const float* __restrict__ x, const float* __restrict__ wg,
                         float* __restrict__ out) {
    const int t = blockIdx.x, tid = threadIdx.x, w = tid >> 5, lane = tid & 31;
    const float* xr = x  + (size_t)t * H;
    // zero out row t
    float4 z = make_float4(0.f, 0.f, 0.f, 0.f);
    *(float4*)(out + (size_t)t * H + tid * 4)        = z;
    *(float4*)(out + (size_t)t * H + 1024 + tid * 4) = z;
    // split x row t into bf16 hi/lo
    #pragma unroll
    for (int i = tid * 4; i < H; i += 1024) {
        float4 v = *(const float4*)(xr + i);
        uint32_t h0, h1, l0, l1;
        split4(v, h0, h1, l0, l1);
        *(uint2*)(g_x_hi + (size_t)t * HW + i / 2) = make_uint2(h0, h1);
        *(uint2*)(g_x_lo + (size_t)t * HW + i / 2) = make_uint2(l0, l1);
    }
    // routing
    const float* gr = wg + (size_t)w * H;
    float s = 0.f;
    for (int i = lane * 4; i < H; i += 128) {
        float4 xv = *(const float4*)(xr + i);
        float4 gv = *(const float4*)(gr + i);
        s += xv.x * gv.x + xv.y * gv.y + xv.z * gv.z + xv.w * gv.w;
    }
    #pragma unroll
    for (int o = 16; o; o >>= 1) s += __shfl_xor_sync(0xffffffffu, s, o);
    __shared__ float lg[E];
    if (lane == 0) lg[w] = s;
    __syncthreads();
    if (tid == 0) {
        float mx = lg[0];
        #pragma unroll
        for (int e = 1; e < E; e++) mx = fmaxf(mx, lg[e]);
        float ex[E];
        #pragma unroll
        for (int e = 0; e < E; e++) ex[e] = expf(lg[e] - mx);
        int i0 = 0;
        #pragma unroll
        for (int e = 1; e < E; e++) if (ex[e] > ex[i0]) i0 = e;
        int i1 = (i0 == 0) ? 1 : 0;
        #pragma unroll
        for (int e = 0; e < E; e++) if (e != i0 && ex[e] > ex[i1]) i1 = e;
        float s0 = ex[i0], s1 = ex[i1], inv = 1.f / (s0 + s1);
        int p0 = atomicAdd(&g_cnt[i0], 1);
        g_tok[i0][p0] = t;  g_cw[i0][p0] = s0 * inv;
        int p1 = atomicAdd(&g_cnt[i1], 1);
        g_tok[i1][p1] = t;  g_cw[i1][p1] = s1 * inv;
    }
}

// issue cp.async for stage kt: A (bf16 hi/lo) + B (raw fp32); always commits.
#define ISSUE(kt_)                                                              \
    do {                                                                        \
        if ((kt_) < KT) {                                                       \
            const uint32_t st = sbase + (((kt_) % 3) << 14);                    \
            const char* sh = (const char*)(arow_hi + (kt_) * 16 + h * 8);       \
            const char* sl = (const char*)(arow_lo + (kt_) * 16 + h * 8);       \
            uint32_t da = st + a_dst0;                                          \
            CP16(da,           sh);                                             \
            CP16(da ^ 16,      sh + 16);                                        \
            CP16(da ^ 64,      sl);                                             \
            CP16(da ^ 64 ^ 16, sl + 16);                                        \
            const char* sb = (const char*)(bsrc + (size_t)(kt_) * 32);          \
            uint32_t db = st + 0xC000 + b_dst0;                                 \
            CP16(db,      sb);                                                  \
            CP16(db ^ 16, sb + 16);                                             \
            CP16(db ^ 32, sb + 32);                                             \
            CP16(db ^ 48, sb + 48);                                             \
        }                                                                       \
        CPCOMMIT();                                                             \
    } while (0)

// 64m x 32n warp tile; A via ldmatrix (bf16 hi/lo tile), B frags built from fp32 smem.
#define COMPUTE(aoff_, bfp_)                                                    \
    {                                                                           \
        _Pragma("unroll")                                                       \
        for (int kk = 0; kk < 2; kk++) {                                        \
            uint32_t Ah[4][4], Al[4][4];                                        \
            _Pragma("unroll")                                                   \
            for (int mt = 0; mt < 4; mt++) {                                    \
                uint32_t oa = (a_swb + mt * 2048) ^ (kk << 5);                  \
                ldsm4(Ah[mt], (aoff_) + oa);                                    \
                ldsm4(Al[mt], (aoff_) + (oa ^ 64));                             \
            }                                                                   \
            _Pragma("unroll")                                                   \
            for (int f = 0; f < 4; f++) {                                       \
                uint32_t rb = (bfp_) + b_rowoff + f * 1024;                     \
                float2 p0 = lds64(rb + (((kk << 6) + b_k0) ^ b_sw));            \
                float2 p1 = lds64(rb + (((kk << 6) + b_k0 + 32) ^ b_sw));       \
                uint32_t bh0, bl0, bh1, bl1;                                    \
                split2(p0, bh0, bl0);                                           \
                split2(p1, bh1, bl1);                                           \
                _Pragma("unroll")                                               \
                for (int mt = 0; mt < 4; mt++) mma_bf(acc[mt][f], Ah[mt], bh0, bh1); \
                _Pragma("unroll")                                               \
                for (int mt = 0; mt < 4; mt++) mma_bf(acc[mt][f], Ah[mt], bl0, bl1); \
                _Pragma("unroll")                                               \
                for (int mt = 0; mt < 4; mt++) mma_bf(acc[mt][f], Al[mt], bh0, bh1); \
            }                                                                   \
        }                                                                       \
    }

// ---------------- GEMM1: act = silu(x@Wg^T)*(x@Wu^T) ----------------
// block 128m x 128 B-rows (64 gate + 64 up -> 64 act cols), BK=32
__global__ void __launch_bounds__(256, 2) k_gemm1(const float* __restrict__ w1) {
    const int e = blockIdx.z, cnt = g_cnt[e];
    const int m0 = blockIdx.y * 128;
    if (m0 >= cnt) return;
    const int n0 = blockIdx.x * 64;

    extern __shared__ char sm[];
    const uint32_t sbase = smem_u32(sm);
    __shared__ int s_tok[128];

    const int tid = threadIdx.x, lane = tid & 31, wid = tid >> 5;
    if (tid < 128) { int r = m0 + tid; if (r >= cnt) r = cnt - 1; s_tok[tid] = g_tok[e][r]; }
    __syncthreads();

    // A cp.async: 2 thr/row (row = tid>>1), h = half
    const int lrow = tid >> 1, h = tid & 1;
    const uint32_t* arow_hi = g_x_hi + (size_t)s_tok[lrow] * HW;
    const uint32_t* arow_lo = g_x_lo + (size_t)s_tok[lrow] * HW;
    const uint32_t a_dst0 = (uint32_t)lrow * 128 + (((uint32_t)h * 32) ^ (((uint32_t)lrow & 7) << 4));
    // B cp.async: 2 thr/row, 64B each (fp32)
    const int brow = lrow;
    const int wrow = (brow < 64) ? (n0 + brow) : (I + n0 + brow - 64);
    const float* bsrc = w1 + ((size_t)e * I2 + wrow) * H + h * 16;
    const uint32_t b_dst0 = (uint32_t)brow * 128 + (((uint32_t)h * 64) ^ (((uint32_t)brow & 7) << 4));
    // fragment bases
    const int wm = (wid & 1) * 64, wn = (wid >> 1) * 32;
    const uint32_t a_row = wm + (lane & 15);
    const uint32_t a_swb = (a_row * 128 + ((lane >> 4) << 4)) ^ ((a_row & 7) << 4);
    const uint32_t b_rowoff = (uint32_t)(wn + (lane >> 2)) * 128;
    const uint32_t b_k0 = ((uint32_t)lane & 3) * 8;
    const uint32_t b_sw = (((uint32_t)lane >> 2) & 7) << 4;

    float acc[4][4][4] = {};
    const int KT = H / 32;

    ISSUE(0);
    ISSUE(1);
    for (int kt = 0; kt < KT; kt++) {
        CPWAIT(1);
        __syncthreads();
        ISSUE(kt + 2);
        const uint32_t aoff = sbase + ((kt % 3) << 14);
        const uint32_t bfp  = aoff + 0xC000;
        COMPUTE(aoff, bfp);
    }

    // epilogue: stage D [128][132] f32, recombine gate/up, split, store act
    CPWAIT(0);
    __syncthreads();
    float* stg = (float*)sm;
    #pragma unroll
    for (int mt = 0; mt < 4; mt++)
        #pragma unroll
        for (int f = 0; f < 4; f++) {
            int r = wm + mt * 16 + (lane >> 2);
            int c = wn + f * 8 + (lane & 3) * 2;
            stg[r * 132 + c]           = acc[mt][f][0];
            stg[r * 132 + c + 1]       = acc[mt][f][1];
            stg[(r + 8) * 132 + c]     = acc[mt][f][2];
            stg[(r + 8) * 132 + c + 1] = acc[mt][f][3];
        }
    __syncthreads();
    const int erow = tid >> 1, grow = m0 + erow;
    if (grow < cnt) {
        const int pb = (tid & 1) * 16;
        uint32_t hw[16], lw[16];
        #pragma unroll
        for (int j = 0; j < 16; j++) {
            int p = pb + j;
            float g0 = stg[erow * 132 + 2 * p],      g1 = stg[erow * 132 + 2 * p + 1];
            float u0 = stg[erow * 132 + 64 + 2 * p], u1 = stg[erow * 132 + 65 + 2 * p];
            float a0 = g0 / (1.f + __expf(-g0)) * u0;
            float a1 = g1 / (1.f + __expf(-g1)) * u1;
            uint32_t hh = packbf(a0, a1);
            hw[j] = hh;
            lw[j] = packbf(a0 - __uint_as_float(hh << 16),
                           a1 - __uint_as_float(hh & 0xFFFF0000u));
        }
        size_t base = ((size_t)e * T + grow) * IW + (n0 >> 1) + pb;
        #pragma unroll
        for (int q = 0; q < 4; q++) {
            *(uint4*)(g_act_hi + base + 4 * q) = make_uint4(hw[4*q], hw[4*q+1], hw[4*q+2], hw[4*q+3]);
            *(uint4*)(g_act_lo + base + 4 * q) = make_uint4(lw[4*q], lw[4*q+1], lw[4*q+2], lw[4*q+3]);
        }
    }
}

// ---------------- GEMM2: out[tok] += cw * (act @ W2^T) ----------------
// block 128m x 128n, BK=32
__global__ void __launch_bounds__(256, 2) k_gemm2(const float* __restrict__ w2,
                                                  float* __restrict__ out) {
    const int e = blockIdx.z, cnt = g_cnt[e];
    const int m0 = blockIdx.y * 128;
    if (m0 >= cnt) return;
    const int n0 = blockIdx.x * 128;

    extern __shared__ char sm[];
    const uint32_t sbase = smem_u32(sm);
    __shared__ int   s_tok[128];
    __shared__ float s_cw [128];

    const int tid = threadIdx.x, lane = tid & 31, wid = tid >> 5;
    if (tid < 128) {
        int r = m0 + tid, rr = (r < cnt) ? r : (cnt - 1);
        s_tok[tid] = g_tok[e][rr];
        s_cw [tid] = (r < cnt) ? g_cw[e][r] : 0.f;
    }
    __syncthreads();

    const int lrow = tid >> 1, h = tid & 1;
    int ar = m0 + lrow; if (ar >= cnt) ar = cnt - 1;
    const uint32_t* arow_hi = g_act_hi + ((size_t)e * T + g_tok[e][0] * 0 + ar) * IW;
    const uint32_t* arow_lo = g_act_lo + ((size_t)e * T + ar) * IW;
    const uint32_t a_dst0 = (uint32_t)lrow * 128 + (((uint32_t)h * 32) ^ (((uint32_t)lrow & 7) << 4));
    const float* bsrc = w2 + ((size_t)e * H + n0 + lrow) * I + h * 16;
    const uint32_t b_dst0 = (uint32_t)lrow * 128 + (((uint32_t)h * 64) ^ (((uint32_t)lrow & 7) << 4));

    const int wm = (wid & 1) * 64, wn = (wid >> 1) * 32;
    const uint32_t a_row = wm + (lane & 15);
    const uint32_t a_swb = (a_row * 128 + ((lane >> 4) << 4)) ^ ((a_row & 7) << 4);
    const uint32_t b_rowoff = (uint32_t)(wn + (lane >> 2)) * 128;
    const uint32_t b_k0 = ((uint32_t)lane & 3) * 8;
    const uint32_t b_sw = (((uint32_t)lane >> 2) & 7) << 4;

    float acc[4][4][4] = {};
    const int KT = I / 32;

    ISSUE(0);
    ISSUE(1);
    for (int kt = 0; kt < KT; kt++) {
        CPWAIT(1);
        __syncthreads();
        ISSUE(kt + 2);
        const uint32_t aoff = sbase + ((kt % 3) << 14);
        const uint32_t bfp  = aoff + 0xC000;
        COMPUTE(aoff, bfp);
    }
    CPWAIT(0);

    // epilogue: scale + atomicAdd (each out element receives exactly 2 adds total)
    #pragma unroll
    for (int mt = 0; mt < 4; mt++)
        #pragma unroll
        for (int f = 0; f < 4; f++) {
            int r = wm + mt * 16 + (lane >> 2);
            int c = n0 + wn + f * 8 + (lane & 3) * 2;
            if (m0 + r < cnt) {
                float cw = s_cw[r];
                float* op = out + (size_t)s_tok[r] * H + c;
                atomicAdd(op,     acc[mt][f][0] * cw);
                atomicAdd(op + 1, acc[mt][f][1] * cw);
            }
            if (m0 + r + 8 < cnt) {
                float cw = s_cw[r + 8];
                float* op = out + (size_t)s_tok[r + 8] * H + c;
                atomicAdd(op,     acc[mt][f][2] * cw);
                atomicAdd(op + 1, acc[mt][f][3] * cw);
            }
        }
}

// ---------------- launch ----------------
extern "C" void kernel_launch(void* const* d_in, const int* in_sizes, int n_in,
                              void* d_out, int out_size) {
    const float* x  = (const float*)d_in[0];   // [T, H]
    const float* w1 = (const float*)d_in[1];   // [E, 2I, H]
    const float* w2 = (const float*)d_in[2];   // [E, H, I]
    const float* wg = (const float*)d_in[3];   // [E, H]
    float* out = (float*)d_out;                // [T, 1, H]

    cudaFuncSetAttribute(k_gemm1, cudaFuncAttributeMaxDynamicSharedMemorySize, SMEMSZ);
    cudaFuncSetAttribute(k_gemm2, cudaFuncAttributeMaxDynamicSharedMemorySize, SMEMSZ);

    k_init<<<1, 32>>>();
    k_router<<<T, 256>>>(x, wg, out);
    k_gemm1<<<dim3(I / 64, (T + 127) / 128, E), 256, SMEMSZ>>>(w1);
    k_gemm2<<<dim3(H / 128, (T + 127) / 128, E), 256, SMEMSZ>>>(w2, out);
}

// round 8
// speedup vs baseline: 1.5451x; 1.5451x over previous
#include <cuda_runtime.h>
#include <cuda_fp16.h>
#include <cstdint>

#define H   2048
#define I   1408
#define E   8
#define T   512
#define I2  2816   // 2*I
#define IW  704    // I/2: act row width in uint32 (fp16 pairs)
#define HW  1024   // H/2: x row width in uint32 (fp16 pairs)

// per-CTA dynamic smem: A fp16 ring 3x8KB @0, B fp16 double 2x8KB @0x6000
#define A_STG(k) ((((k) % 3)) << 13)
#define B_BUF(b) (0x6000 + ((b) << 13))
#define SMEMSZ   0xA000   // 40 KB

// ---------------- device scratch (no allocations allowed) ----------------
__device__ int   g_cnt[E];
__device__ int   g_tok[E][T];
__device__ float g_cw [E][T];
__device__ __align__(16) uint32_t g_act_hi[(size_t)E * T * IW];
__device__ __align__(16) uint32_t g_act_lo[(size_t)E * T * IW];
__device__ __align__(16) uint32_t g_x_hi[(size_t)T * HW];
__device__ __align__(16) uint32_t g_x_lo[(size_t)T * HW];

// ---------------- helpers ----------------
__device__ __forceinline__ uint32_t smem_u32(const void* p) {
    uint32_t a;
    asm("{ .reg .u64 t; cvta.to.shared.u64 t, %1; cvt.u32.u64 %0, t; }" : "=r"(a) : "l"(p));
    return a;
}
// pack two fp32 -> fp16x2 (first arg in low 16 bits)
__device__ __forceinline__ uint32_t packh(float lo, float hi) {
    uint32_t r;
    asm("cvt.rn.f16x2.f32 %0, %1, %2;" : "=r"(r) : "f"(hi), "f"(lo));
    return r;
}
__device__ __forceinline__ float2 unpackh(uint32_t u) {
    __half2 h = *reinterpret_cast<__half2*>(&u);
    return __half22float2(h);
}
// exact split: v = hi(fp16) + lo(fp16 residual)
__device__ __forceinline__ void split4h(float4 v, uint32_t& h0, uint32_t& h1,
                                        uint32_t& l0, uint32_t& l1) {
    h0 = packh(v.x, v.y);
    h1 = packh(v.z, v.w);
    float2 f0 = unpackh(h0), f1 = unpackh(h1);
    l0 = packh(v.x - f0.x, v.y - f0.y);
    l1 = packh(v.z - f1.x, v.w - f1.y);
}
__device__ __forceinline__ void ldsm4(uint32_t* r, uint32_t a) {
    asm volatile("ldmatrix.sync.aligned.m8n8.x4.shared.b16 {%0,%1,%2,%3}, [%4];"
        : "=r"(r[0]), "=r"(r[1]), "=r"(r[2]), "=r"(r[3]) : "r"(a));
}
__device__ __forceinline__ void mma_h(float* d, const uint32_t* a, uint32_t b0, uint32_t b1) {
    asm volatile("mma.sync.aligned.m16n8k16.row.col.f32.f16.f16.f32 "
        "{%0,%1,%2,%3}, {%4,%5,%6,%7}, {%8,%9}, {%0,%1,%2,%3};"
        : "+f"(d[0]), "+f"(d[1]), "+f"(d[2]), "+f"(d[3])
        : "r"(a[0]), "r"(a[1]), "r"(a[2]), "r"(a[3]), "r"(b0), "r"(b1));
}
#define CP16(d_, s_)  asm volatile("cp.async.cg.shared.global [%0], [%1], 16;" :: "r"(d_), "l"(s_))
#define CPCOMMIT()    asm volatile("cp.async.commit_group;" ::)
#define CPWAIT(n_)    asm volatile("cp.async.wait_group %0;" :: "n"(n_))

// ---------------- init ----------------
__global__ void k_init() {
    if (threadIdx.x < E) g_cnt[threadIdx.x] = 0;
}

// ---------------- router: zero out row, split x row to fp16 hi/lo, route ----------------
__global__ void k_router(const float* __restrict__ x, const float* __restrict__ wg,
                         float* __restrict__ out) {
    const int t = blockIdx.x, tid = threadIdx.x, w = tid >> 5, lane = tid & 31;
    const float* xr = x + (size_t)t * H;
    float4 z = make_float4(0.f, 0.f, 0.f, 0.f);
    *(float4*)(out + (size_t)t * H + tid * 4)        = z;
    *(float4*)(out + (size_t)t * H + 1024 + tid * 4) = z;
    #pragma unroll
    for (int i = tid * 4; i < H; i += 1024) {
        float4 v = *(const float4*)(xr + i);
        uint32_t h0, h1, l0, l1;
        split4h(v, h0, h1, l0, l1);
        *(uint2*)(g_x_hi + (size_t)t * HW + i / 2) = make_uint2(h0, h1);
        *(uint2*)(g_x_lo + (size_t)t * HW + i / 2) = make_uint2(l0, l1);
    }
    const float* gr = wg + (size_t)w * H;
    float s = 0.f;
    for (int i = lane * 4; i < H; i += 128) {
        float4 xv = *(const float4*)(xr + i);
        float4 gv = *(const float4*)(gr + i);
        s += xv.x * gv.x + xv.y * gv.y + xv.z * gv.z + xv.w * gv.w;
    }
    #pragma unroll
    for (int o = 16; o; o >>= 1) s += __shfl_xor_sync(0xffffffffu, s, o);
    __shared__ float lg[E];
    if (lane == 0) lg[w] = s;
    __syncthreads();
    if (tid == 0) {
        float mx = lg[0];
        #pragma unroll
        for (int e = 1; e < E; e++) mx = fmaxf(mx, lg[e]);
        float ex[E];
        #pragma unroll
        for (int e = 0; e < E; e++) ex[e] = expf(lg[e] - mx);
        int i0 = 0;
        #pragma unroll
        for (int e = 1; e < E; e++) if (ex[e] > ex[i0]) i0 = e;
        int i1 = (i0 == 0) ? 1 : 0;
        #pragma unroll
        for (int e = 0; e < E; e++) if (e != i0 && ex[e] > ex[i1]) i1 = e;
        float s0 = ex[i0], s1 = ex[i1], inv = 1.f / (s0 + s1);
        int p0 = atomicAdd(&g_cnt[i0], 1);
        g_tok[i0][p0] = t;  g_cw[i0][p0] = s0 * inv;
        int p1 = atomicAdd(&g_cnt[i1], 1);
        g_tok[i1][p1] = t;  g_cw[i1][p1] = s1 * inv;
    }
}

// A cp.async (4 thr/row): one 16B hi + one 16B lo per thread per stage
#define ISSUE_A(kt_)                                                            \
    do {                                                                        \
        if ((kt_) < KT) {                                                       \
            uint32_t da = sbase + A_STG(kt_) + a_dst0;                          \
            CP16(da,      (const char*)(arow_hi + (kt_) * 16 + q * 4));         \
            CP16(da ^ 64, (const char*)(arow_lo + (kt_) * 16 + q * 4));         \
        }                                                                       \
        CPCOMMIT();                                                             \
    } while (0)

// B prefetch: 16 floats per thread (2 thr/row over 128 rows)
#define LDG_B(kt_)                                                              \
    { const float* p = bptr + (size_t)(kt_) * 32;                               \
      bv[0] = *(const float4*)p;       bv[1] = *(const float4*)(p + 4);         \
      bv[2] = *(const float4*)(p + 8); bv[3] = *(const float4*)(p + 12); }

// convert 16 fp32 -> 16 fp16, store two 16B chunks into 64B-row B tile
#define STS_B(b_)                                                               \
    { char* s = sm + B_BUF(b_);                                                 \
      uint32_t u[8];                                                            \
      _Pragma("unroll")                                                         \
      for (int i = 0; i < 4; i++) {                                             \
          u[2*i]   = packh(bv[i].x, bv[i].y);                                   \
          u[2*i+1] = packh(bv[i].z, bv[i].w);                                   \
      }                                                                         \
      *(uint4*)(s + b_sts0)        = make_uint4(u[0], u[1], u[2], u[3]);        \
      *(uint4*)(s + (b_sts0 ^ 16)) = make_uint4(u[4], u[5], u[6], u[7]);        \
    }

// 32m x 128n block compute per warp: warp tile 32x32 (wm 2x32, wn 4x32), 2-pass fp16
#define COMPUTE(aoff_, boff_)                                                   \
    {                                                                           \
        _Pragma("unroll")                                                       \
        for (int kk = 0; kk < 2; kk++) {                                        \
            uint32_t Ah[2][4], Al[2][4], Bh[2][4];                              \
            _Pragma("unroll")                                                   \
            for (int mt = 0; mt < 2; mt++) {                                    \
                uint32_t oa = (a_swb + mt * 2048) ^ (kk << 5);                  \
                ldsm4(Ah[mt], (aoff_) + oa);                                    \
                ldsm4(Al[mt], (aoff_) + (oa ^ 64));                             \
            }                                                                   \
            _Pragma("unroll")                                                   \
            for (int n2 = 0; n2 < 2; n2++)                                      \
                ldsm4(Bh[n2], (boff_) + ((b_swb + n2 * 1024) ^ (kk << 5)));     \
            _Pragma("unroll")                                                   \
            for (int mt = 0; mt < 2; mt++)                                      \
                _Pragma("unroll")                                               \
                for (int n2 = 0; n2 < 2; n2++) {                                \
                    mma_h(acc[mt][2*n2],   Ah[mt], Bh[n2][0], Bh[n2][1]);       \
                    mma_h(acc[mt][2*n2+1], Ah[mt], Bh[n2][2], Bh[n2][3]);       \
                }                                                               \
            _Pragma("unroll")                                                   \
            for (int mt = 0; mt < 2; mt++)                                      \
                _Pragma("unroll")                                               \
                for (int n2 = 0; n2 < 2; n2++) {                                \
                    mma_h(acc[mt][2*n2],   Al[mt], Bh[n2][0], Bh[n2][1]);       \
                    mma_h(acc[mt][2*n2+1], Al[mt], Bh[n2][2], Bh[n2][3]);       \
                }                                                               \
        }                                                                       \
    }

// ---------------- GEMM1: act = silu(x@Wg^T)*(x@Wu^T) ----------------
// block 64m x 128 B-rows (64 gate + 64 up -> 64 act cols), BK=32, 8 warps (2m x 4n)
__global__ void __launch_bounds__(256, 2) k_gemm1(const float* __restrict__ w1) {
    const int e = blockIdx.z, cnt = g_cnt[e];
    const int m0 = blockIdx.y * 64;
    if (m0 >= cnt) return;
    const int n0 = blockIdx.x * 64;

    extern __shared__ char sm[];
    const uint32_t sbase = smem_u32(sm);
    __shared__ int s_tok[64];

    const int tid = threadIdx.x, lane = tid & 31, wid = tid >> 5;
    if (tid < 64) { int r = m0 + tid; if (r >= cnt) r = cnt - 1; s_tok[tid] = g_tok[e][r]; }
    __syncthreads();

    // A loader: 4 thr/row
    const int lrow = tid >> 2, q = tid & 3;
    const uint32_t* arow_hi = g_x_hi + (size_t)s_tok[lrow] * HW;
    const uint32_t* arow_lo = g_x_lo + (size_t)s_tok[lrow] * HW;
    const uint32_t a_dst0 = (uint32_t)lrow * 128 + (((uint32_t)q * 16) ^ (((uint32_t)lrow & 7) << 4));
    // B loader: 2 thr/row over 128 rows (64 gate + 64 up)
    const int brow = tid >> 1, bh = tid & 1;
    const int wrow = (brow < 64) ? (n0 + brow) : (I + n0 + brow - 64);
    const float* bptr = w1 + ((size_t)e * I2 + wrow) * H + bh * 16;
    const uint32_t b_sts0 = (uint32_t)brow * 64 +
        (((uint32_t)bh << 5) ^ ((((uint32_t)brow >> 1) & 3) << 4));
    // fragment bases
    const int wm = (wid & 1) * 32, wn = (wid >> 1) * 32;
    const uint32_t a_row = wm + (lane & 15);
    const uint32_t a_swb = (a_row * 128 + ((lane >> 4) << 4)) ^ ((a_row & 7) << 4);
    const uint32_t b_row = wn + (lane & 7) + ((lane >> 4) << 3);
    const uint32_t b_swb = (b_row * 64 + (((lane >> 3) & 1) << 4)) ^ (((b_row >> 1) & 3) << 4);

    float acc[2][4][4] = {};
    float4 bv[4];
    const int KT = H / 32;

    ISSUE_A(0);
    ISSUE_A(1);
    LDG_B(0);
    STS_B(0);

    for (int kt = 0; kt < KT; kt++) {
        if (kt + 1 < KT) LDG_B(kt + 1);
        CPWAIT(1);
        __syncthreads();
        ISSUE_A(kt + 2);
        COMPUTE(sbase + A_STG(kt), sbase + B_BUF(kt & 1));
        if (kt + 1 < KT) STS_B((kt + 1) & 1);
    }

    // epilogue: stage D [64][132], recombine gate/up, split fp16, store act
    CPWAIT(0);
    __syncthreads();
    float* stg = (float*)sm;
    #pragma unroll
    for (int mt = 0; mt < 2; mt++)
        #pragma unroll
        for (int f = 0; f < 4; f++) {
            int r = wm + mt * 16 + (lane >> 2);
            int c = wn + f * 8 + (lane & 3) * 2;
            stg[r * 132 + c]           = acc[mt][f][0];
            stg[r * 132 + c + 1]       = acc[mt][f][1];
            stg[(r + 8) * 132 + c]     = acc[mt][f][2];
            stg[(r + 8) * 132 + c + 1] = acc[mt][f][3];
        }
    __syncthreads();
    const int erow = tid >> 2, grow = m0 + erow;
    if (grow < cnt) {
        const int pc = (tid & 3) * 16;   // act col base (16 cols = 8 uint32)
        uint32_t hw[8], lw[8];
        #pragma unroll
        for (int j = 0; j < 8; j++) {
            int c0 = pc + 2 * j;
            float g0 = stg[erow * 132 + c0],      g1 = stg[erow * 132 + c0 + 1];
            float u0 = stg[erow * 132 + 64 + c0], u1 = stg[erow * 132 + 65 + c0];
            float a0 = g0 / (1.f + __expf(-g0)) * u0;
            float a1 = g1 / (1.f + __expf(-g1)) * u1;
            uint32_t hh = packh(a0, a1);
            float2 f2 = unpackh(hh);
            hw[j] = hh;
            lw[j] = packh(a0 - f2.x, a1 - f2.y);
        }
        size_t base = ((size_t)e * T + grow) * IW + (n0 >> 1) + (pc >> 1);
        *(uint4*)(g_act_hi + base)     = make_uint4(hw[0], hw[1], hw[2], hw[3]);
        *(uint4*)(g_act_hi + base + 4) = make_uint4(hw[4], hw[5], hw[6], hw[7]);
        *(uint4*)(g_act_lo + base)     = make_uint4(lw[0], lw[1], lw[2], lw[3]);
        *(uint4*)(g_act_lo + base + 4) = make_uint4(lw[4], lw[5], lw[6], lw[7]);
    }
}

// ---------------- GEMM2: out[tok] += cw * (act @ W2^T) ----------------
// block 64m x 128n, BK=32, 8 warps (2m x 4n), warp tile 32x32
__global__ void __launch_bounds__(256, 2) k_gemm2(const float* __restrict__ w2,
                                                  float* __restrict__ out) {
    const int e = blockIdx.z, cnt = g_cnt[e];
    const int m0 = blockIdx.y * 64;
    if (m0 >= cnt) return;
    const int n0 = blockIdx.x * 128;

    extern __shared__ char sm[];
    const uint32_t sbase = smem_u32(sm);
    __shared__ int   s_tok[64];
    __shared__ float s_cw [64];

    const int tid = threadIdx.x, lane = tid & 31, wid = tid >> 5;
    if (tid < 64) {
        int r = m0 + tid, rr = (r < cnt) ? r : (cnt - 1);
        s_tok[tid] = g_tok[e][rr];
        s_cw [tid] = (r < cnt) ? g_cw[e][r] : 0.f;
    }
    __syncthreads();

    const int lrow = tid >> 2, q = tid & 3;
    int ar = m0 + lrow; if (ar >= cnt) ar = cnt - 1;
    const uint32_t* arow_hi = g_act_hi + ((size_t)e * T + ar) * IW;
    const uint32_t* arow_lo = g_act_lo + ((size_t)e * T + ar) * IW;
    const uint32_t a_dst0 = (uint32_t)lrow * 128 + (((uint32_t)q * 16) ^ (((uint32_t)lrow & 7) << 4));
    const int brow = tid >> 1, bh = tid & 1;
    const float* bptr = w2 + ((size_t)e * H + n0 + brow) * I + bh * 16;
    const uint32_t b_sts0 = (uint32_t)brow * 64 +
        (((uint32_t)bh << 5) ^ ((((uint32_t)brow >> 1) & 3) << 4));

    const int wm = (wid & 1) * 32, wn = (wid >> 1) * 32;
    const uint32_t a_row = wm + (lane & 15);
    const uint32_t a_swb = (a_row * 128 + ((lane >> 4) << 4)) ^ ((a_row & 7) << 4);
    const uint32_t b_row = wn + (lane & 7) + ((lane >> 4) << 3);
    const uint32_t b_swb = (b_row * 64 + (((lane >> 3) & 1) << 4)) ^ (((b_row >> 1) & 3) << 4);

    float acc[2][4][4] = {};
    float4 bv[4];
    const int KT = I / 32;

    ISSUE_A(0);
    ISSUE_A(1);
    LDG_B(0);
    STS_B(0);

    for (int kt = 0; kt < KT; kt++) {
        if (kt + 1 < KT) LDG_B(kt + 1);
        CPWAIT(1);
        __syncthreads();
        ISSUE_A(kt + 2);
        COMPUTE(sbase + A_STG(kt), sbase + B_BUF(kt & 1));
        if (kt + 1 < KT) STS_B((kt + 1) & 1);
    }
    CPWAIT(0);

    // epilogue: scale + atomicAdd (each out element receives exactly 2 adds total)
    #pragma unroll
    for (int mt = 0; mt < 2; mt++)
        #pragma unroll
        for (int f = 0; f < 4; f++) {
            int r = wm + mt * 16 + (lane >> 2);
            int c = n0 + wn + f * 8 + (lane & 3) * 2;
            if (m0 + r < cnt) {
                float cw = s_cw[r];
                float* op = out + (size_t)s_tok[r] * H + c;
                atomicAdd(op,     acc[mt][f][0] * cw);
                atomicAdd(op + 1, acc[mt][f][1] * cw);
            }
            if (m0 + r + 8 < cnt) {
                float cw = s_cw[r + 8];
                float* op = out + (size_t)s_tok[r + 8] * H + c;
                atomicAdd(op,     acc[mt][f][2] * cw);
                atomicAdd(op + 1, acc[mt][f][3] * cw);
            }
        }
}

// ---------------- launch ----------------
extern "C" void kernel_launch(void* const* d_in, const int* in_sizes, int n_in,
                              void* d_out, int out_size) {
    const float* x  = (const float*)d_in[0];   // [T, H]
    const float* w1 = (const float*)d_in[1];   // [E, 2I, H]
    const float* w2 = (const float*)d_in[2];   // [E, H, I]
    const float* wg = (const float*)d_in[3];   // [E, H]
    float* out = (float*)d_out;                // [T, 1, H]

    cudaFuncSetAttribute(k_gemm1, cudaFuncAttributeMaxDynamicSharedMemorySize, SMEMSZ);
    cudaFuncSetAttribute(k_gemm2, cudaFuncAttributeMaxDynamicSharedMemorySize, SMEMSZ);

    k_init<<<1, 32>>>();
    k_router<<<T, 256>>>(x, wg, out);
    k_gemm1<<<dim3(I / 64, (T + 63) / 64, E), 256, SMEMSZ>>>(w1);
    k_gemm2<<<dim3(H / 128, (T + 63) / 64, E), 256, SMEMSZ>>>(w2, out);
}

// round 9
// speedup vs baseline: 1.8129x; 1.1734x over previous
#include <cuda_runtime.h>
#include <cuda_fp16.h>
#include <cstdint>

#define H   2048
#define I   1408
#define E   8
#define T   512
#define I2  2816   // 2*I
#define IW  704    // I/2: act row width in uint32 (fp16 pairs)
#define HW  1024   // H/2: x row width in uint32 (fp16 pairs)

// per-CTA dynamic smem: A fp16 ring 3x4KB @0, B fp16 double 2x8KB @0x3000
#define A_STG(k) ((((k) % 3)) << 12)
#define B_BUF(b) (0x3000 + ((b) << 13))
#define SMEMSZ   0x8800   // 34 KB (gemm1 epilogue stage needs 64*132*4 = 33792)

// ---------------- device scratch (no allocations allowed) ----------------
__device__ int   g_cnt[E];
__device__ int   g_tok[E][T];
__device__ float g_cw [E][T];
__device__ __align__(16) uint32_t g_act[(size_t)E * T * IW];  // fp16 pairs
__device__ __align__(16) uint32_t g_x  [(size_t)T * HW];      // fp16 pairs

// ---------------- helpers ----------------
__device__ __forceinline__ uint32_t smem_u32(const void* p) {
    uint32_t a;
    asm("{ .reg .u64 t; cvta.to.shared.u64 t, %1; cvt.u32.u64 %0, t; }" : "=r"(a) : "l"(p));
    return a;
}
// pack two fp32 -> fp16x2 (first arg in low 16 bits)
__device__ __forceinline__ uint32_t packh(float lo, float hi) {
    uint32_t r;
    asm("cvt.rn.f16x2.f32 %0, %1, %2;" : "=r"(r) : "f"(hi), "f"(lo));
    return r;
}
__device__ __forceinline__ void ldsm4(uint32_t* r, uint32_t a) {
    asm volatile("ldmatrix.sync.aligned.m8n8.x4.shared.b16 {%0,%1,%2,%3}, [%4];"
        : "=r"(r[0]), "=r"(r[1]), "=r"(r[2]), "=r"(r[3]) : "r"(a));
}
__device__ __forceinline__ void mma_h(float* d, const uint32_t* a, uint32_t b0, uint32_t b1) {
    asm volatile("mma.sync.aligned.m16n8k16.row.col.f32.f16.f16.f32 "
        "{%0,%1,%2,%3}, {%4,%5,%6,%7}, {%8,%9}, {%0,%1,%2,%3};"
        : "+f"(d[0]), "+f"(d[1]), "+f"(d[2]), "+f"(d[3])
        : "r"(a[0]), "r"(a[1]), "r"(a[2]), "r"(a[3]), "r"(b0), "r"(b1));
}
#define CP16(d_, s_)  asm volatile("cp.async.cg.shared.global [%0], [%1], 16;" :: "r"(d_), "l"(s_))
#define CPCOMMIT()    asm volatile("cp.async.commit_group;" ::)
#define CPWAIT(n_)    asm volatile("cp.async.wait_group %0;" :: "n"(n_))

// ---------------- init ----------------
__global__ void k_init() {
    if (threadIdx.x < E) g_cnt[threadIdx.x] = 0;
}

// ---------------- router: zero out row, convert x row to fp16, route ----------------
__global__ void k_router(const float* __restrict__ x, const float* __restrict__ wg,
                         float* __restrict__ out) {
    const int t = blockIdx.x, tid = threadIdx.x, w = tid >> 5, lane = tid & 31;
    const float* xr = x + (size_t)t * H;
    float4 z = make_float4(0.f, 0.f, 0.f, 0.f);
    *(float4*)(out + (size_t)t * H + tid * 4)        = z;
    *(float4*)(out + (size_t)t * H + 1024 + tid * 4) = z;
    #pragma unroll
    for (int i = tid * 4; i < H; i += 1024) {
        float4 v = *(const float4*)(xr + i);
        *(uint2*)(g_x + (size_t)t * HW + i / 2) =
            make_uint2(packh(v.x, v.y), packh(v.z, v.w));
    }
    const float* gr = wg + (size_t)w * H;
    float s = 0.f;
    for (int i = lane * 4; i < H; i += 128) {
        float4 xv = *(const float4*)(xr + i);
        float4 gv = *(const float4*)(gr + i);
        s += xv.x * gv.x + xv.y * gv.y + xv.z * gv.z + xv.w * gv.w;
    }
    #pragma unroll
    for (int o = 16; o; o >>= 1) s += __shfl_xor_sync(0xffffffffu, s, o);
    __shared__ float lg[E];
    if (lane == 0) lg[w] = s;
    __syncthreads();
    if (tid == 0) {
        float mx = lg[0];
        #pragma unroll
        for (int e = 1; e < E; e++) mx = fmaxf(mx, lg[e]);
        float ex[E];
        #pragma unroll
        for (int e = 0; e < E; e++) ex[e] = expf(lg[e] - mx);
        int i0 = 0;
        #pragma unroll
        for (int e = 1; e < E; e++) if (ex[e] > ex[i0]) i0 = e;
        int i1 = (i0 == 0) ? 1 : 0;
        #pragma unroll
        for (int e = 0; e < E; e++) if (e != i0 && ex[e] > ex[i1]) i1 = e;
        float s0 = ex[i0], s1 = ex[i1], inv = 1.f / (s0 + s1);
        int p0 = atomicAdd(&g_cnt[i0], 1);
        g_tok[i0][p0] = t;  g_cw[i0][p0] = s0 * inv;
        int p1 = atomicAdd(&g_cnt[i1], 1);
        g_tok[i1][p1] = t;  g_cw[i1][p1] = s1 * inv;
    }
}

// A cp.async (4 thr/row, 16B each): 64 rows x 64B fp16 per stage
#define ISSUE_A(kt_)                                                            \
    do {                                                                        \
        if ((kt_) < KT) {                                                       \
            uint32_t da = sbase + A_STG(kt_) + a_dst0;                          \
            CP16(da, (const char*)(arow + (kt_) * 16 + q * 4));                 \
        }                                                                       \
        CPCOMMIT();                                                             \
    } while (0)

// B prefetch: 16 floats per thread (2 thr/row over 128 rows)
#define LDG_B(kt_)                                                              \
    { const float* p = bptr + (size_t)(kt_) * 32;                               \
      bv[0] = *(const float4*)p;       bv[1] = *(const float4*)(p + 4);         \
      bv[2] = *(const float4*)(p + 8); bv[3] = *(const float4*)(p + 12); }

// convert 16 fp32 -> 16 fp16, store two 16B chunks into 64B-row B tile
#define STS_B(b_)                                                               \
    { char* s = sm + B_BUF(b_);                                                 \
      uint32_t u[8];                                                            \
      _Pragma("unroll")                                                         \
      for (int i = 0; i < 4; i++) {                                             \
          u[2*i]   = packh(bv[i].x, bv[i].y);                                   \
          u[2*i+1] = packh(bv[i].z, bv[i].w);                                   \
      }                                                                         \
      *(uint4*)(s + b_sts0)        = make_uint4(u[0], u[1], u[2], u[3]);        \
      *(uint4*)(s + (b_sts0 ^ 16)) = make_uint4(u[4], u[5], u[6], u[7]);        \
    }

// warp tile 32m x 32n, single-pass fp16; A tile 64B rows, B tile 64B rows
#define COMPUTE(aoff_, boff_)                                                   \
    {                                                                           \
        _Pragma("unroll")                                                       \
        for (int kk = 0; kk < 2; kk++) {                                        \
            uint32_t Ah[2][4], Bh[2][4];                                        \
            _Pragma("unroll")                                                   \
            for (int mt = 0; mt < 2; mt++)                                      \
                ldsm4(Ah[mt], (aoff_) + ((a_swb + mt * 1024) ^ (kk << 5)));     \
            _Pragma("unroll")                                                   \
            for (int n2 = 0; n2 < 2; n2++)                                      \
                ldsm4(Bh[n2], (boff_) + ((b_swb + n2 * 1024) ^ (kk << 5)));     \
            _Pragma("unroll")                                                   \
            for (int mt = 0; mt < 2; mt++)                                      \
                _Pragma("unroll")                                               \
                for (int n2 = 0; n2 < 2; n2++) {                                \
                    mma_h(acc[mt][2*n2],   Ah[mt], Bh[n2][0], Bh[n2][1]);       \
                    mma_h(acc[mt][2*n2+1], Ah[mt], Bh[n2][2], Bh[n2][3]);       \
                }                                                               \
        }                                                                       \
    }

// ---------------- GEMM1: act = silu(x@Wg^T)*(x@Wu^T) ----------------
// block 64m x 128 B-rows (64 gate + 64 up -> 64 act cols), BK=32, 8 warps (2m x 4n)
__global__ void __launch_bounds__(256, 2) k_gemm1(const float* __restrict__ w1) {
    const int e = blockIdx.z, cnt = g_cnt[e];
    const int m0 = blockIdx.y * 64;
    if (m0 >= cnt) return;
    const int n0 = blockIdx.x * 64;

    extern __shared__ char sm[];
    const uint32_t sbase = smem_u32(sm);
    __shared__ int s_tok[64];

    const int tid = threadIdx.x, lane = tid & 31, wid = tid >> 5;
    if (tid < 64) { int r = m0 + tid; if (r >= cnt) r = cnt - 1; s_tok[tid] = g_tok[e][r]; }
    __syncthreads();

    // A loader: 4 thr/row, 16B each
    const int lrow = tid >> 2, q = tid & 3;
    const uint32_t* arow = g_x + (size_t)s_tok[lrow] * HW;
    const uint32_t a_dst0 = (uint32_t)lrow * 64 +
        (((uint32_t)q * 16) ^ ((((uint32_t)lrow >> 1) & 3) << 4));
    // B loader: 2 thr/row over 128 rows (64 gate + 64 up)
    const int brow = tid >> 1, bh = tid & 1;
    const int wrow = (brow < 64) ? (n0 + brow) : (I + n0 + brow - 64);
    const float* bptr = w1 + ((size_t)e * I2 + wrow) * H + bh * 16;
    const uint32_t b_sts0 = (uint32_t)brow * 64 +
        (((uint32_t)bh << 5) ^ ((((uint32_t)brow >> 1) & 3) << 4));
    // fragment bases
    const int wm = (wid & 1) * 32, wn = (wid >> 1) * 32;
    const uint32_t a_row = wm + (lane & 15);
    const uint32_t a_swb = a_row * 64 +
        ((((uint32_t)lane >> 4) << 4) ^ (((a_row >> 1) & 3) << 4));
    const uint32_t b_row = wn + (lane & 7) + ((lane >> 4) << 3);
    const uint32_t b_swb = b_row * 64 +
        (((((uint32_t)lane >> 3) & 1) << 4) ^ (((b_row >> 1) & 3) << 4));

    float acc[2][4][4] = {};
    float4 bv[4];
    const int KT = H / 32;

    ISSUE_A(0);
    ISSUE_A(1);
    LDG_B(0);
    STS_B(0);

    for (int kt = 0; kt < KT; kt++) {
        if (kt + 1 < KT) LDG_B(kt + 1);
        CPWAIT(1);
        __syncthreads();
        ISSUE_A(kt + 2);
        COMPUTE(sbase + A_STG(kt), sbase + B_BUF(kt & 1));
        if (kt + 1 < KT) STS_B((kt + 1) & 1);
    }

    // epilogue: stage D [64][132], recombine gate/up, fp16 pack, store act
    CPWAIT(0);
    __syncthreads();
    float* stg = (float*)sm;
    #pragma unroll
    for (int mt = 0; mt < 2; mt++)
        #pragma unroll
        for (int f = 0; f < 4; f++) {
            int r = wm + mt * 16 + (lane >> 2);
            int c = wn + f * 8 + (lane & 3) * 2;
            stg[r * 132 + c]           = acc[mt][f][0];
            stg[r * 132 + c + 1]       = acc[mt][f][1];
            stg[(r + 8) * 132 + c]     = acc[mt][f][2];
            stg[(r + 8) * 132 + c + 1] = acc[mt][f][3];
        }
    __syncthreads();
    const int erow = tid >> 2, grow = m0 + erow;
    if (grow < cnt) {
        const int pc = (tid & 3) * 16;   // act col base (16 cols = 8 uint32)
        uint32_t hw[8];
        #pragma unroll
        for (int j = 0; j < 8; j++) {
            int c0 = pc + 2 * j;
            float g0 = stg[erow * 132 + c0],      g1 = stg[erow * 132 + c0 + 1];
            float u0 = stg[erow * 132 + 64 + c0], u1 = stg[erow * 132 + 65 + c0];
            float a0 = g0 / (1.f + __expf(-g0)) * u0;
            float a1 = g1 / (1.f + __expf(-g1)) * u1;
            hw[j] = packh(a0, a1);
        }
        size_t base = ((size_t)e * T + grow) * IW + (n0 >> 1) + (pc >> 1);
        *(uint4*)(g_act + base)     = make_uint4(hw[0], hw[1], hw[2], hw[3]);
        *(uint4*)(g_act + base + 4) = make_uint4(hw[4], hw[5], hw[6], hw[7]);
    }
}

// ---------------- GEMM2: out[tok] += cw * (act @ W2^T) ----------------
// block 64m x 128n, BK=32, 8 warps (2m x 4n), warp tile 32x32
__global__ void __launch_bounds__(256, 2) k_gemm2(const float* __restrict__ w2,
                                                  float* __restrict__ out) {
    const int e = blockIdx.z, cnt = g_cnt[e];
    const int m0 = blockIdx.y * 64;
    if (m0 >= cnt) return;
    const int n0 = blockIdx.x * 128;

    extern __shared__ char sm[];
    const uint32_t sbase = smem_u32(sm);
    __shared__ int   s_tok[64];
    __shared__ float s_cw [64];

    const int tid = threadIdx.x, lane = tid & 31, wid = tid >> 5;
    if (tid < 64) {
        int r = m0 + tid, rr = (r < cnt) ? r : (cnt - 1);
        s_tok[tid] = g_tok[e][rr];
        s_cw [tid] = (r < cnt) ? g_cw[e][r] : 0.f;
    }
    __syncthreads();

    const int lrow = tid >> 2, q = tid & 3;
    int ar = m0 + lrow; if (ar >= cnt) ar = cnt - 1;
    const uint32_t* arow = g_act + ((size_t)e * T + ar) * IW;
    const uint32_t a_dst0 = (uint32_t)lrow * 64 +
        (((uint32_t)q * 16) ^ ((((uint32_t)lrow >> 1) & 3) << 4));
    const int brow = tid >> 1, bh = tid & 1;
    const float* bptr = w2 + ((size_t)e * H + n0 + brow) * I + bh * 16;
    const uint32_t b_sts0 = (uint32_t)brow * 64 +
        (((uint32_t)bh << 5) ^ ((((uint32_t)brow >> 1) & 3) << 4));

    const int wm = (wid & 1) * 32, wn = (wid >> 1) * 32;
    const uint32_t a_row = wm + (lane & 15);
    const uint32_t a_swb = a_row * 64 +
        ((((uint32_t)lane >> 4) << 4) ^ (((a_row >> 1) & 3) << 4));
    const uint32_t b_row = wn + (lane & 7) + ((lane >> 4) << 3);
    const uint32_t b_swb = b_row * 64 +
        (((((uint32_t)lane >> 3) & 1) << 4) ^ (((b_row >> 1) & 3) << 4));

    float acc[2][4][4] = {};
    float4 bv[4];
    const int KT = I / 32;

    ISSUE_A(0);
    ISSUE_A(1);
    LDG_B(0);
    STS_B(0);

    for (int kt = 0; kt < KT; kt++) {
        if (kt + 1 < KT) LDG_B(kt + 1);
        CPWAIT(1);
        __syncthreads();
        ISSUE_A(kt + 2);
        COMPUTE(sbase + A_STG(kt), sbase + B_BUF(kt & 1));
        if (kt + 1 < KT) STS_B((kt + 1) & 1);
    }
    CPWAIT(0);

    // epilogue: scale + atomicAdd (each out element receives exactly 2 adds total)
    #pragma unroll
    for (int mt = 0; mt < 2; mt++)
        #pragma unroll
        for (int f = 0; f < 4; f++) {
            int r = wm + mt * 16 + (lane >> 2);
            int c = n0 + wn + f * 8 + (lane & 3) * 2;
            if (m0 + r < cnt) {
                float cw = s_cw[r];
                float* op = out + (size_t)s_tok[r] * H + c;
                atomicAdd(op,     acc[mt][f][0] * cw);
                atomicAdd(op + 1, acc[mt][f][1] * cw);
            }
            if (m0 + r + 8 < cnt) {
                float cw = s_cw[r + 8];
                float* op = out + (size_t)s_tok[r + 8] * H + c;
                atomicAdd(op,     acc[mt][f][2] * cw);
                atomicAdd(op + 1, acc[mt][f][3] * cw);
            }
        }
}

// ---------------- launch ----------------
extern "C" void kernel_launch(void* const* d_in, const int* in_sizes, int n_in,
                              void* d_out, int out_size) {
    const float* x  = (const float*)d_in[0];   // [T, H]
    const float* w1 = (const float*)d_in[1];   // [E, 2I, H]
    const float* w2 = (const float*)d_in[2];   // [E, H, I]
    const float* wg = (const float*)d_in[3];   // [E, H]
    float* out = (float*)d_out;                // [T, 1, H]

    cudaFuncSetAttribute(k_gemm1, cudaFuncAttributeMaxDynamicSharedMemorySize, SMEMSZ);
    cudaFuncSetAttribute(k_gemm2, cudaFuncAttributeMaxDynamicSharedMemorySize, SMEMSZ);

    k_init<<<1, 32>>>();
    k_router<<<T, 256>>>(x, wg, out);
    k_gemm1<<<dim3(I / 64, (T + 63) / 64, E), 256, SMEMSZ>>>(w1);
    k_gemm2<<<dim3(H / 128, (T + 63) / 64, E), 256, SMEMSZ>>>(w2, out);
}